// round 3
// baseline (speedup 1.0000x reference)
#include <cuda_runtime.h>
#include <math.h>

#define Bn 4
#define Nn 4096
#define En 16384

// ---------------------------------------------------------------------------
// Static device scratch
// ---------------------------------------------------------------------------
__device__ __align__(16) float g_P[(size_t)64 * Nn * 256];     // [b*16+t][n][i]
__device__ __align__(16) float g_AG[(size_t)Bn * Nn * 768];    // [a_in | a_out | h or r*h]
__device__ __align__(16) float g_RZ[(size_t)Bn * Nn * 512];    // [r | z]
__device__ __align__(16) float g_h[(size_t)Bn * Nn * 256];     // node state (tf32-rounded)
__device__ __align__(16) float g_ann[(size_t)Bn * Nn * 64];
__device__ __align__(16) float g_Wt[16 * 256 * 256];           // rounded edge_embed
__device__ __align__(16) float g_Wrz[512 * 768];               // rounded [Wr;Wz]
__device__ __align__(16) float g_Wh[256 * 768];                // rounded Wh
__device__ __align__(16) float g_brz[512];
__device__ float g_nodeval[Bn * Nn];

// ---------------------------------------------------------------------------
// Helpers
// ---------------------------------------------------------------------------
__device__ __forceinline__ unsigned f2tf(float x) {
    unsigned r;
    asm("cvt.rna.tf32.f32 %0, %1;" : "=r"(r) : "f"(x));
    return r;
}
__device__ __forceinline__ float roundtf(float x) { return __uint_as_float(f2tf(x)); }

__device__ __forceinline__ void mma1688(float* c, const unsigned* a, const unsigned* b) {
    asm volatile(
        "mma.sync.aligned.m16n8k8.row.col.f32.tf32.tf32.f32 "
        "{%0,%1,%2,%3}, {%4,%5,%6,%7}, {%8,%9}, {%0,%1,%2,%3};"
        : "+f"(c[0]), "+f"(c[1]), "+f"(c[2]), "+f"(c[3])
        : "r"(a[0]), "r"(a[1]), "r"(a[2]), "r"(a[3]), "r"(b[0]), "r"(b[1]));
}

__device__ __forceinline__ void cpasync16(unsigned saddr, const float* gptr) {
    asm volatile("cp.async.cg.shared.global [%0], [%1], 16;" :: "r"(saddr), "l"(gptr));
}
__device__ __forceinline__ void cpcommit() { asm volatile("cp.async.commit_group;"); }
__device__ __forceinline__ void cpwait1() { asm volatile("cp.async.wait_group 1;"); }
__device__ __forceinline__ void cpwait0() { asm volatile("cp.async.wait_group 0;"); }

#define SMS 40            // smem row stride (floats): 160B, 16B-aligned, conflict-free
#define SMEM_BYTES (2 * 2 * 128 * SMS * 4)   // 81920

// ---------------------------------------------------------------------------
// TF32 GEMM core: C[m,n] = act( sum_k A[m,k]*B[n,k] + bias[n] )
// Block 128x128, BK=32, 256 thr = 8 warps (2m x 4n), warp 64x32, 2-stage cp.async.
// ACT: 0 none(+round), 1 sigmoid, 2 tanh + fused h-update.
// k-slots are consumed in a permuted order (identical for A and B => same sum):
//   mma-k slot (ks,u): u<4 -> smem col ks*8+2u ; u>=4 -> col ks*8+2(u-4)+1
// so each thread's (tg, tg+4) fragment pair is one ld.shared.v2.
// ---------------------------------------------------------------------------
template <int ACT>
__device__ __forceinline__ void gemm_core(const float* __restrict__ A, int lda,
                                          const float* __restrict__ B, int ldb,
                                          float* __restrict__ C, int ldc,
                                          const float* __restrict__ bias, int K,
                                          const float* __restrict__ Zp,   // z (stride 512)
                                          float* __restrict__ Hp)         // h (stride 256)
{
    extern __shared__ float sm[];
    float* As = sm;                    // [2][128][SMS]
    float* Bs = sm + 2 * 128 * SMS;

    const int tid = threadIdx.x;
    const int wid = tid >> 5, lane = tid & 31;
    const int g = lane >> 2, tg = lane & 3;
    const int wm = (wid >> 2) * 64;
    const int wn = (wid & 3) * 32;
    const int m0 = blockIdx.x * 128;
    const int n0 = blockIdx.y * 128;

    // fill mapping: thread -> (row, 16-float half)
    const int frow = tid >> 1;
    const int fcol = (tid & 1) * 16;
    const float* Ag = A + (size_t)(m0 + frow) * lda + fcol;
    const float* Bg = B + (size_t)(n0 + frow) * ldb + fcol;
    unsigned sA = (unsigned)__cvta_generic_to_shared(As + frow * SMS + fcol);
    unsigned sB = (unsigned)__cvta_generic_to_shared(Bs + frow * SMS + fcol);
    const unsigned stgOff = 128 * SMS * 4;  // bytes per stage

    float acc[4][4][4];
#pragma unroll
    for (int mt = 0; mt < 4; mt++)
#pragma unroll
        for (int nt = 0; nt < 4; nt++)
#pragma unroll
            for (int c = 0; c < 4; c++) acc[mt][nt][c] = 0.f;

    const int KT = K >> 5;

    // prologue: stage 0
#pragma unroll
    for (int j = 0; j < 4; j++) {
        cpasync16(sA + j * 16, Ag + j * 4);
        cpasync16(sB + j * 16, Bg + j * 4);
    }
    cpcommit();

    for (int kt = 0; kt < KT; kt++) {
        if (kt + 1 < KT) {
            const float* Ag2 = Ag + (kt + 1) * 32;
            const float* Bg2 = Bg + (kt + 1) * 32;
            unsigned off = ((kt + 1) & 1) * stgOff;
#pragma unroll
            for (int j = 0; j < 4; j++) {
                cpasync16(sA + off + j * 16, Ag2 + j * 4);
                cpasync16(sB + off + j * 16, Bg2 + j * 4);
            }
            cpcommit();
            cpwait1();
        } else {
            cpwait0();
        }
        __syncthreads();

        const float* Ac = As + (kt & 1) * 128 * SMS;
        const float* Bc = Bs + (kt & 1) * 128 * SMS;
#pragma unroll
        for (int ks = 0; ks < 4; ks++) {
            const int kc = ks * 8 + 2 * tg;
            unsigned af[4][4], bf[4][2];
#pragma unroll
            for (int mt = 0; mt < 4; mt++) {
                int row = wm + mt * 16 + g;
                float2 lo = *(const float2*)(Ac + row * SMS + kc);
                float2 hi = *(const float2*)(Ac + (row + 8) * SMS + kc);
                af[mt][0] = __float_as_uint(lo.x);
                af[mt][1] = __float_as_uint(hi.x);
                af[mt][2] = __float_as_uint(lo.y);
                af[mt][3] = __float_as_uint(hi.y);
            }
#pragma unroll
            for (int nt = 0; nt < 4; nt++) {
                int col = wn + nt * 8 + g;
                float2 b = *(const float2*)(Bc + col * SMS + kc);
                bf[nt][0] = __float_as_uint(b.x);
                bf[nt][1] = __float_as_uint(b.y);
            }
#pragma unroll
            for (int mt = 0; mt < 4; mt++)
#pragma unroll
                for (int nt = 0; nt < 4; nt++)
                    mma1688(acc[mt][nt], af[mt], bf[nt]);
        }
        __syncthreads();
    }

    // epilogue
#pragma unroll
    for (int mt = 0; mt < 4; mt++) {
#pragma unroll
        for (int nt = 0; nt < 4; nt++) {
            int row = m0 + wm + mt * 16 + g;
            int col = n0 + wn + nt * 8 + 2 * tg;
            float b0 = bias ? bias[col] : 0.f;
            float b1 = bias ? bias[col + 1] : 0.f;
            float v0 = acc[mt][nt][0] + b0, v1 = acc[mt][nt][1] + b1;
            float v2 = acc[mt][nt][2] + b0, v3 = acc[mt][nt][3] + b1;
            if (ACT == 0) {
                float* p = C + (size_t)row * ldc + col;
                *(float2*)p = make_float2(roundtf(v0), roundtf(v1));
                *(float2*)(p + (size_t)8 * ldc) = make_float2(roundtf(v2), roundtf(v3));
            } else if (ACT == 1) {
                float* p = C + (size_t)row * ldc + col;
                *(float2*)p = make_float2(1.f / (1.f + expf(-v0)), 1.f / (1.f + expf(-v1)));
                *(float2*)(p + (size_t)8 * ldc) =
                    make_float2(1.f / (1.f + expf(-v2)), 1.f / (1.f + expf(-v3)));
            } else {  // fused GRU update: h = (1-z)h + z*tanh(v), tf32-rounded
                float z0 = Zp[(size_t)row * 512 + col], z1 = Zp[(size_t)row * 512 + col + 1];
                float z2 = Zp[(size_t)(row + 8) * 512 + col], z3 = Zp[(size_t)(row + 8) * 512 + col + 1];
                float* hp0 = Hp + (size_t)row * 256 + col;
                float* hp1 = Hp + (size_t)(row + 8) * 256 + col;
                float h0 = hp0[0], h1 = hp0[1], h2 = hp1[0], h3 = hp1[1];
                *(float2*)hp0 = make_float2(roundtf((1.f - z0) * h0 + z0 * tanhf(v0)),
                                            roundtf((1.f - z1) * h1 + z1 * tanhf(v1)));
                *(float2*)hp1 = make_float2(roundtf((1.f - z2) * h2 + z2 * tanhf(v2)),
                                            roundtf((1.f - z3) * h3 + z3 * tanhf(v3)));
            }
        }
    }
}

// ---------------------------------------------------------------------------
// GEMM wrappers
// ---------------------------------------------------------------------------
__global__ void __launch_bounds__(256, 2) gemmP_k() {
    int z = blockIdx.z;
    int b = z >> 4, t = z & 15;
    gemm_core<0>(g_h + (size_t)b * Nn * 256, 256,
                 g_Wt + (size_t)t * 65536, 256,
                 g_P + (size_t)z * Nn * 256, 256, nullptr, 256, nullptr, nullptr);
}

__global__ void __launch_bounds__(256, 2) gemm_rz_k() {
    gemm_core<1>(g_AG, 768, g_Wrz, 768, g_RZ, 512, g_brz, 768, nullptr, nullptr);
}

__global__ void __launch_bounds__(256, 2) gemm_hh_k(const float* __restrict__ bh) {
    gemm_core<2>(g_AG, 768, g_Wh, 768, nullptr, 0, bh, 768, g_RZ + 256, g_h);
}

// ---------------------------------------------------------------------------
// Setup kernels
// ---------------------------------------------------------------------------
__global__ void prep_Wt(const float* __restrict__ ee) {
    size_t i = (size_t)blockIdx.x * 256 + threadIdx.x;  // 1M elems
    g_Wt[i] = roundtf(ee[i]);
}

__global__ void prep_Wrz(const float* __restrict__ Wr, const float* __restrict__ Wz,
                         const float* __restrict__ br, const float* __restrict__ bz) {
    int r = blockIdx.x;  // 512
    const float* s = (r < 256) ? (Wr + (size_t)r * 768) : (Wz + (size_t)(r - 256) * 768);
    for (int c = threadIdx.x; c < 768; c += blockDim.x)
        g_Wrz[(size_t)r * 768 + c] = roundtf(s[c]);
    if (threadIdx.x == 0) g_brz[r] = (r < 256) ? br[r] : bz[r - 256];
}

__global__ void prep_Wh(const float* __restrict__ Wh) {
    size_t i = (size_t)blockIdx.x * 256 + threadIdx.x;  // 768 blocks
    g_Wh[i] = roundtf(Wh[i]);
}

__global__ void init_h(const int* __restrict__ ann_id, const float* __restrict__ te) {
    int n = blockIdx.x;
    int i = threadIdx.x;
    int id = ann_id[n];
    float a = 0.f;
    if (i < 64 && id > 0) a = te[(size_t)(id - 1) * 64 + i];
    if (i < 64) g_ann[(size_t)n * 64 + i] = a;
    g_h[(size_t)n * 256 + i] = (i < 64) ? roundtf(a) : 0.f;
}

// ---------------------------------------------------------------------------
// Per-step kernels
// ---------------------------------------------------------------------------
__global__ void prep_AG() {
    int n = blockIdx.x;
    int i = threadIdx.x;
    float* ag = g_AG + (size_t)n * 768;
    ag[i] = 0.f;
    ag[256 + i] = 0.f;
    ag[512 + i] = g_h[(size_t)n * 256 + i];
}

__global__ void __launch_bounds__(128) scatter_k(const int* __restrict__ src,
                                                 const int* __restrict__ dst,
                                                 const int* __restrict__ et,
                                                 const float* __restrict__ eb) {
    int e = blockIdx.x;
    int b = e >> 14;
    int tid = threadIdx.x;
    int dir = tid >> 6, q = tid & 63;
    int s = __ldg(&src[e]);
    int d = __ldg(&dst[e]);
    int t = __ldg(&et[e]);
    const float4* P4 = (const float4*)g_P;
    const float4* eb4 = (const float4*)eb;
    float4 v, bb;
    float* tgt;
    if (dir == 0) {
        v = P4[(((size_t)(b * 16 + t) * Nn + d) << 6) + q];
        bb = eb4[t * 64 + q];
        tgt = g_AG + (size_t)(b * Nn + s) * 768 + 256 + q * 4;
    } else {
        v = P4[(((size_t)(b * 16 + t + 8) * Nn + s) << 6) + q];
        bb = eb4[(t + 8) * 64 + q];
        tgt = g_AG + (size_t)(b * Nn + d) * 768 + q * 4;
    }
    v.x += bb.x; v.y += bb.y; v.z += bb.z; v.w += bb.w;
    asm volatile("red.global.add.v4.f32 [%0], {%1,%2,%3,%4};"
                 :: "l"(tgt), "f"(v.x), "f"(v.y), "f"(v.z), "f"(v.w)
                 : "memory");
}

__global__ void set_rh() {
    int n = blockIdx.x;
    int i = threadIdx.x;
    float r = g_RZ[(size_t)n * 512 + i];
    g_AG[(size_t)n * 768 + 512 + i] = roundtf(r * g_h[(size_t)n * 256 + i]);
}

// ---------------------------------------------------------------------------
// Readout
// ---------------------------------------------------------------------------
__global__ void readout_k(const float* __restrict__ Wa, const float* __restrict__ ba,
                          const float* __restrict__ Wo, const float* __restrict__ bo) {
    int warp = (blockIdx.x * blockDim.x + threadIdx.x) >> 5;
    int lane = threadIdx.x & 31;
    const float* hrow = g_h + (size_t)warp * 256;
    const float* arow = g_ann + (size_t)warp * 64;
    float sa = 0.f, so = 0.f;
#pragma unroll
    for (int k = lane; k < 320; k += 32) {
        float v = (k < 256) ? hrow[k] : arow[k - 256];
        sa += v * Wa[k];
        so += v * Wo[k];
    }
#pragma unroll
    for (int off = 16; off; off >>= 1) {
        sa += __shfl_xor_sync(0xffffffffu, sa, off);
        so += __shfl_xor_sync(0xffffffffu, so, off);
    }
    if (lane == 0) {
        float atten = 1.f / (1.f + expf(-(sa + ba[0])));
        float ou = tanhf(so + bo[0]);
        g_nodeval[warp] = atten * ou;
    }
}

__global__ void finalize_k(float* __restrict__ out) {
    __shared__ float sh[256];
    int b = blockIdx.x;
    float s = 0.f;
    for (int i = threadIdx.x; i < Nn; i += 256) s += g_nodeval[(size_t)b * Nn + i];
    sh[threadIdx.x] = s;
    __syncthreads();
    for (int k = 128; k; k >>= 1) {
        if (threadIdx.x < k) sh[threadIdx.x] += sh[threadIdx.x + k];
        __syncthreads();
    }
    if (threadIdx.x == 0) out[b] = 1.f / (1.f + expf(-sh[0]));
}

// ---------------------------------------------------------------------------
// Launch
// ---------------------------------------------------------------------------
extern "C" void kernel_launch(void* const* d_in, const int* in_sizes, int n_in,
                              void* d_out, int out_size) {
    (void)in_sizes; (void)n_in; (void)out_size;
    const int* ann_id = (const int*)d_in[0];
    const int* src    = (const int*)d_in[1];
    const int* dst    = (const int*)d_in[2];
    const int* et     = (const int*)d_in[3];
    const float* ee   = (const float*)d_in[4];
    const float* eb   = (const float*)d_in[5];
    const float* te   = (const float*)d_in[6];
    const float* Wr   = (const float*)d_in[7];
    const float* br   = (const float*)d_in[8];
    const float* Wz   = (const float*)d_in[9];
    const float* bz   = (const float*)d_in[10];
    const float* Wh   = (const float*)d_in[11];
    const float* bh   = (const float*)d_in[12];
    const float* Wa   = (const float*)d_in[13];
    const float* ba   = (const float*)d_in[14];
    const float* Wo   = (const float*)d_in[15];
    const float* bo   = (const float*)d_in[16];
    float* out = (float*)d_out;

    cudaFuncSetAttribute(gemmP_k, cudaFuncAttributeMaxDynamicSharedMemorySize, SMEM_BYTES);
    cudaFuncSetAttribute(gemm_rz_k, cudaFuncAttributeMaxDynamicSharedMemorySize, SMEM_BYTES);
    cudaFuncSetAttribute(gemm_hh_k, cudaFuncAttributeMaxDynamicSharedMemorySize, SMEM_BYTES);

    prep_Wt<<<4096, 256>>>(ee);
    prep_Wrz<<<512, 256>>>(Wr, Wz, br, bz);
    prep_Wh<<<768, 256>>>(Wh);
    init_h<<<Bn * Nn, 256>>>(ann_id, te);

    for (int step = 0; step < 3; step++) {
        prep_AG<<<Bn * Nn, 256>>>();
        gemmP_k<<<dim3(32, 2, 64), 256, SMEM_BYTES>>>();
        scatter_k<<<Bn * En, 128>>>(src, dst, et, eb);
        gemm_rz_k<<<dim3(128, 4, 1), 256, SMEM_BYTES>>>();
        set_rh<<<Bn * Nn, 256>>>();
        gemm_hh_k<<<dim3(128, 2, 1), 256, SMEM_BYTES>>>(bh);
    }

    readout_k<<<2048, 256>>>(Wa, ba, Wo, bo);
    finalize_k<<<4, 256>>>(out);
}

// round 4
// speedup vs baseline: 1.4527x; 1.4527x over previous
#include <cuda_runtime.h>
#include <math.h>

#define Bn 4
#define Nn 4096
#define En 16384

// ---------------------------------------------------------------------------
// Static device scratch
// ---------------------------------------------------------------------------
__device__ __align__(16) float g_P[(size_t)64 * Nn * 256];     // [b*16+t][n][i]
__device__ __align__(16) float g_AG[(size_t)Bn * Nn * 768];    // [a_in | a_out | h or r*h]
__device__ __align__(16) float g_RZ[(size_t)Bn * Nn * 512];    // z in cols 256..511
__device__ __align__(16) float g_h[(size_t)Bn * Nn * 256];     // node state (tf32-rounded)
__device__ __align__(16) float g_ann[(size_t)Bn * Nn * 64];
__device__ __align__(16) float g_Wt[16 * 256 * 256];           // rounded edge_embed
__device__ __align__(16) float g_Wrz[512 * 768];               // rounded [Wr;Wz]
__device__ __align__(16) float g_Wh[256 * 768];                // rounded Wh
__device__ __align__(16) float g_brz[512];
__device__ float g_nodeval[Bn * Nn];

// ---------------------------------------------------------------------------
// Helpers
// ---------------------------------------------------------------------------
__device__ __forceinline__ unsigned f2tf(float x) {
    unsigned r;
    asm("cvt.rna.tf32.f32 %0, %1;" : "=r"(r) : "f"(x));
    return r;
}
__device__ __forceinline__ float roundtf(float x) { return __uint_as_float(f2tf(x)); }

__device__ __forceinline__ void mma1688(float* c, const unsigned* a, const unsigned* b) {
    asm volatile(
        "mma.sync.aligned.m16n8k8.row.col.f32.tf32.tf32.f32 "
        "{%0,%1,%2,%3}, {%4,%5,%6,%7}, {%8,%9}, {%0,%1,%2,%3};"
        : "+f"(c[0]), "+f"(c[1]), "+f"(c[2]), "+f"(c[3])
        : "r"(a[0]), "r"(a[1]), "r"(a[2]), "r"(a[3]), "r"(b[0]), "r"(b[1]));
}

#define SMS 36                      // [m][k] row stride (floats): conflict-free scalar LDS
#define STAGE (128 * SMS)           // floats per stage per operand
#define SMEM_BYTES (4 * STAGE * 4)  // 2 stages x (A+B) = 73728 B

// ---------------------------------------------------------------------------
// TF32 GEMM core: C[m,n] = act( sum_k A[m,k]*B[n,k] + bias[n] )
// Block 128x128, BK=32, 256 thr = 8 warps (2m x 4n), warp 64x32.
// Double-buffered smem, register prefetch, ONE __syncthreads per k-tile:
//     STS(regs -> buf kt&1); LDG(kt+1 -> regs); sync; mma(buf kt&1)
// Layout [m][k] stride 36: scalar frag LDS banks = (4g+tg) mod 32, conflict-free.
// ACT: 0 = round+store; 1 = rz fused (r*h -> AG slot2, z -> C); 2 = hh fused GRU update.
// ---------------------------------------------------------------------------
template <int ACT>
__device__ __forceinline__ void gemm_core(const float* __restrict__ A, int lda,
                                          const float* __restrict__ B, int ldb,
                                          float* __restrict__ C, int ldc,
                                          const float* __restrict__ bias, int K,
                                          const float* __restrict__ Zp,   // ACT1: h ; ACT2: z
                                          float* __restrict__ Hp)         // ACT1: AG ; ACT2: h
{
    extern __shared__ float sm[];
    float* As = sm;                 // [2][128][SMS]
    float* Bs = sm + 2 * STAGE;

    const int tid = threadIdx.x;
    const int wid = tid >> 5, lane = tid & 31;
    const int g = lane >> 2, tg = lane & 3;
    const int wm = (wid >> 2) * 64;
    const int wn = (wid & 3) * 32;
    const int m0 = blockIdx.x * 128;
    const int n0 = blockIdx.y * 128;

    const int lr = tid >> 3;           // 0..31
    const int lc = (tid & 7) << 2;     // 0,4,...,28
    const float* Ag = A + (size_t)(m0 + lr) * lda + lc;
    const float* Bg = B + (size_t)(n0 + lr) * ldb + lc;

    float acc[4][4][4];
#pragma unroll
    for (int mt = 0; mt < 4; mt++)
#pragma unroll
        for (int nt = 0; nt < 4; nt++)
#pragma unroll
            for (int c = 0; c < 4; c++) acc[mt][nt][c] = 0.f;

    const int KT = K >> 5;
    float4 pa[4], pb[4];
#pragma unroll
    for (int r = 0; r < 4; r++) {
        pa[r] = *(const float4*)(Ag + (size_t)(r * 32) * lda);
        pb[r] = *(const float4*)(Bg + (size_t)(r * 32) * ldb);
    }

    for (int kt = 0; kt < KT; kt++) {
        float* Aw = As + (kt & 1) * STAGE;
        float* Bw = Bs + (kt & 1) * STAGE;
#pragma unroll
        for (int r = 0; r < 4; r++) {
            *(float4*)(Aw + (lr + r * 32) * SMS + lc) = pa[r];
            *(float4*)(Bw + (lr + r * 32) * SMS + lc) = pb[r];
        }
        if (kt + 1 < KT) {
            const float* Ag2 = Ag + (kt + 1) * 32;
            const float* Bg2 = Bg + (kt + 1) * 32;
#pragma unroll
            for (int r = 0; r < 4; r++) {
                pa[r] = *(const float4*)(Ag2 + (size_t)(r * 32) * lda);
                pb[r] = *(const float4*)(Bg2 + (size_t)(r * 32) * ldb);
            }
        }
        __syncthreads();

        const float* Ac = Aw;
        const float* Bc = Bw;
#pragma unroll
        for (int ks = 0; ks < 4; ks++) {
            const int kc = ks * 8 + tg;
            unsigned bf[4][2];
#pragma unroll
            for (int nt = 0; nt < 4; nt++) {
                int col = wn + nt * 8 + g;
                bf[nt][0] = __float_as_uint(Bc[col * SMS + kc]);
                bf[nt][1] = __float_as_uint(Bc[col * SMS + kc + 4]);
            }
#pragma unroll
            for (int mt = 0; mt < 4; mt++) {
                int row = wm + mt * 16 + g;
                unsigned af[4];
                af[0] = __float_as_uint(Ac[row * SMS + kc]);
                af[1] = __float_as_uint(Ac[(row + 8) * SMS + kc]);
                af[2] = __float_as_uint(Ac[row * SMS + kc + 4]);
                af[3] = __float_as_uint(Ac[(row + 8) * SMS + kc + 4]);
#pragma unroll
                for (int nt = 0; nt < 4; nt++)
                    mma1688(acc[mt][nt], af, bf[nt]);
            }
        }
        __syncthreads();
    }

    // epilogue
#pragma unroll
    for (int mt = 0; mt < 4; mt++) {
#pragma unroll
        for (int nt = 0; nt < 4; nt++) {
            int row = m0 + wm + mt * 16 + g;
            int col = n0 + wn + nt * 8 + 2 * tg;
            float b0 = bias ? bias[col] : 0.f;
            float b1 = bias ? bias[col + 1] : 0.f;
            float v0 = acc[mt][nt][0] + b0, v1 = acc[mt][nt][1] + b1;
            float v2 = acc[mt][nt][2] + b0, v3 = acc[mt][nt][3] + b1;
            if (ACT == 0) {
                float* p = C + (size_t)row * ldc + col;
                *(float2*)p = make_float2(roundtf(v0), roundtf(v1));
                *(float2*)(p + (size_t)8 * ldc) = make_float2(roundtf(v2), roundtf(v3));
            } else if (ACT == 1) {
                // r | z = sigmoid(v)
                float s0 = 1.f / (1.f + expf(-v0)), s1 = 1.f / (1.f + expf(-v1));
                float s2 = 1.f / (1.f + expf(-v2)), s3 = 1.f / (1.f + expf(-v3));
                if (col < 256) {
                    // r half: AG[row][512+col] = round(r * h)
                    const float* h0 = Zp + (size_t)row * 256 + col;
                    const float* h1 = Zp + (size_t)(row + 8) * 256 + col;
                    float* a0 = Hp + (size_t)row * 768 + 512 + col;
                    float* a1 = Hp + (size_t)(row + 8) * 768 + 512 + col;
                    *(float2*)a0 = make_float2(roundtf(s0 * h0[0]), roundtf(s1 * h0[1]));
                    *(float2*)a1 = make_float2(roundtf(s2 * h1[0]), roundtf(s3 * h1[1]));
                } else {
                    float* p = C + (size_t)row * ldc + col;
                    *(float2*)p = make_float2(s0, s1);
                    *(float2*)(p + (size_t)8 * ldc) = make_float2(s2, s3);
                }
            } else {
                // fused GRU update: h = (1-z)h + z*tanh(v), tf32-rounded
                float z0 = Zp[(size_t)row * 512 + col], z1 = Zp[(size_t)row * 512 + col + 1];
                float z2 = Zp[(size_t)(row + 8) * 512 + col], z3 = Zp[(size_t)(row + 8) * 512 + col + 1];
                float* hp0 = Hp + (size_t)row * 256 + col;
                float* hp1 = Hp + (size_t)(row + 8) * 256 + col;
                float h0 = hp0[0], h1 = hp0[1], h2 = hp1[0], h3 = hp1[1];
                *(float2*)hp0 = make_float2(roundtf((1.f - z0) * h0 + z0 * tanhf(v0)),
                                            roundtf((1.f - z1) * h1 + z1 * tanhf(v1)));
                *(float2*)hp1 = make_float2(roundtf((1.f - z2) * h2 + z2 * tanhf(v2)),
                                            roundtf((1.f - z3) * h3 + z3 * tanhf(v3)));
            }
        }
    }
}

// ---------------------------------------------------------------------------
// GEMM wrappers
// ---------------------------------------------------------------------------
__global__ void __launch_bounds__(256, 2) gemmP_k(int K) {
    int z = blockIdx.z;
    int b = z >> 4, t = z & 15;
    gemm_core<0>(g_h + (size_t)b * Nn * 256, 256,
                 g_Wt + (size_t)t * 65536, 256,
                 g_P + (size_t)z * Nn * 256, 256, nullptr, K, nullptr, nullptr);
}

__global__ void __launch_bounds__(256, 2) gemm_rz_k() {
    // z -> g_RZ cols 256..511 ; r*h -> AG slot 2 (fused set_rh)
    gemm_core<1>(g_AG, 768, g_Wrz, 768, g_RZ, 512, g_brz, 768, g_h, g_AG);
}

__global__ void __launch_bounds__(256, 2) gemm_hh_k(const float* __restrict__ bh) {
    gemm_core<2>(g_AG, 768, g_Wh, 768, nullptr, 0, bh, 768, g_RZ + 256, g_h);
}

// ---------------------------------------------------------------------------
// Setup kernels
// ---------------------------------------------------------------------------
__global__ void prep_Wt(const float* __restrict__ ee) {
    size_t i = (size_t)blockIdx.x * 256 + threadIdx.x;
    g_Wt[i] = roundtf(ee[i]);
}

__global__ void prep_Wrz(const float* __restrict__ Wr, const float* __restrict__ Wz,
                         const float* __restrict__ br, const float* __restrict__ bz) {
    int r = blockIdx.x;  // 512
    const float* s = (r < 256) ? (Wr + (size_t)r * 768) : (Wz + (size_t)(r - 256) * 768);
    for (int c = threadIdx.x; c < 768; c += blockDim.x)
        g_Wrz[(size_t)r * 768 + c] = roundtf(s[c]);
    if (threadIdx.x == 0) g_brz[r] = (r < 256) ? br[r] : bz[r - 256];
}

__global__ void prep_Wh(const float* __restrict__ Wh) {
    size_t i = (size_t)blockIdx.x * 256 + threadIdx.x;
    g_Wh[i] = roundtf(Wh[i]);
}

__global__ void init_h(const int* __restrict__ ann_id, const float* __restrict__ te) {
    int n = blockIdx.x;
    int i = threadIdx.x;
    int id = ann_id[n];
    float a = 0.f;
    if (i < 64 && id > 0) a = te[(size_t)(id - 1) * 64 + i];
    if (i < 64) g_ann[(size_t)n * 64 + i] = a;
    g_h[(size_t)n * 256 + i] = (i < 64) ? roundtf(a) : 0.f;
}

// ---------------------------------------------------------------------------
// Per-step kernels
// ---------------------------------------------------------------------------
__global__ void prep_AG() {
    int n = blockIdx.x;
    int i = threadIdx.x;
    float* ag = g_AG + (size_t)n * 768;
    ag[i] = 0.f;
    ag[256 + i] = 0.f;
    ag[512 + i] = g_h[(size_t)n * 256 + i];
}

__global__ void __launch_bounds__(128) scatter_k(const int* __restrict__ src,
                                                 const int* __restrict__ dst,
                                                 const int* __restrict__ et,
                                                 const float* __restrict__ eb) {
    int e = blockIdx.x;
    int b = e >> 14;
    int tid = threadIdx.x;
    int dir = tid >> 6, q = tid & 63;
    int s = __ldg(&src[e]);
    int d = __ldg(&dst[e]);
    int t = __ldg(&et[e]);
    const float4* P4 = (const float4*)g_P;
    const float4* eb4 = (const float4*)eb;
    float4 v, bb;
    float* tgt;
    if (dir == 0) {
        v = P4[(((size_t)(b * 16 + t) * Nn + d) << 6) + q];
        bb = eb4[t * 64 + q];
        tgt = g_AG + (size_t)(b * Nn + s) * 768 + 256 + q * 4;
    } else {
        v = P4[(((size_t)(b * 16 + t + 8) * Nn + s) << 6) + q];
        bb = eb4[(t + 8) * 64 + q];
        tgt = g_AG + (size_t)(b * Nn + d) * 768 + q * 4;
    }
    v.x += bb.x; v.y += bb.y; v.z += bb.z; v.w += bb.w;
    asm volatile("red.global.add.v4.f32 [%0], {%1,%2,%3,%4};"
                 :: "l"(tgt), "f"(v.x), "f"(v.y), "f"(v.z), "f"(v.w)
                 : "memory");
}

// ---------------------------------------------------------------------------
// Readout
// ---------------------------------------------------------------------------
__global__ void readout_k(const float* __restrict__ Wa, const float* __restrict__ ba,
                          const float* __restrict__ Wo, const float* __restrict__ bo) {
    int warp = (blockIdx.x * blockDim.x + threadIdx.x) >> 5;
    int lane = threadIdx.x & 31;
    const float* hrow = g_h + (size_t)warp * 256;
    const float* arow = g_ann + (size_t)warp * 64;
    float sa = 0.f, so = 0.f;
#pragma unroll
    for (int k = lane; k < 320; k += 32) {
        float v = (k < 256) ? hrow[k] : arow[k - 256];
        sa += v * Wa[k];
        so += v * Wo[k];
    }
#pragma unroll
    for (int off = 16; off; off >>= 1) {
        sa += __shfl_xor_sync(0xffffffffu, sa, off);
        so += __shfl_xor_sync(0xffffffffu, so, off);
    }
    if (lane == 0) {
        float atten = 1.f / (1.f + expf(-(sa + ba[0])));
        float ou = tanhf(so + bo[0]);
        g_nodeval[warp] = atten * ou;
    }
}

__global__ void finalize_k(float* __restrict__ out) {
    __shared__ float sh[256];
    int b = blockIdx.x;
    float s = 0.f;
    for (int i = threadIdx.x; i < Nn; i += 256) s += g_nodeval[(size_t)b * Nn + i];
    sh[threadIdx.x] = s;
    __syncthreads();
    for (int k = 128; k; k >>= 1) {
        if (threadIdx.x < k) sh[threadIdx.x] += sh[threadIdx.x + k];
        __syncthreads();
    }
    if (threadIdx.x == 0) out[b] = 1.f / (1.f + expf(-sh[0]));
}

// ---------------------------------------------------------------------------
// Launch
// ---------------------------------------------------------------------------
extern "C" void kernel_launch(void* const* d_in, const int* in_sizes, int n_in,
                              void* d_out, int out_size) {
    (void)in_sizes; (void)n_in; (void)out_size;
    const int* ann_id = (const int*)d_in[0];
    const int* src    = (const int*)d_in[1];
    const int* dst    = (const int*)d_in[2];
    const int* et     = (const int*)d_in[3];
    const float* ee   = (const float*)d_in[4];
    const float* eb   = (const float*)d_in[5];
    const float* te   = (const float*)d_in[6];
    const float* Wr   = (const float*)d_in[7];
    const float* br   = (const float*)d_in[8];
    const float* Wz   = (const float*)d_in[9];
    const float* bz   = (const float*)d_in[10];
    const float* Wh   = (const float*)d_in[11];
    const float* bh   = (const float*)d_in[12];
    const float* Wa   = (const float*)d_in[13];
    const float* ba   = (const float*)d_in[14];
    const float* Wo   = (const float*)d_in[15];
    const float* bo   = (const float*)d_in[16];
    float* out = (float*)d_out;

    cudaFuncSetAttribute(gemmP_k, cudaFuncAttributeMaxDynamicSharedMemorySize, SMEM_BYTES);
    cudaFuncSetAttribute(gemm_rz_k, cudaFuncAttributeMaxDynamicSharedMemorySize, SMEM_BYTES);
    cudaFuncSetAttribute(gemm_hh_k, cudaFuncAttributeMaxDynamicSharedMemorySize, SMEM_BYTES);

    prep_Wt<<<4096, 256>>>(ee);
    prep_Wrz<<<512, 256>>>(Wr, Wz, br, bz);
    prep_Wh<<<768, 256>>>(Wh);
    init_h<<<Bn * Nn, 256>>>(ann_id, te);

    for (int step = 0; step < 3; step++) {
        prep_AG<<<Bn * Nn, 256>>>();
        // step 0: h only has 64 nonzero columns -> K=64 is exact
        gemmP_k<<<dim3(32, 2, 64), 256, SMEM_BYTES>>>(step == 0 ? 64 : 256);
        scatter_k<<<Bn * En, 128>>>(src, dst, et, eb);
        gemm_rz_k<<<dim3(128, 4, 1), 256, SMEM_BYTES>>>();
        gemm_hh_k<<<dim3(128, 2, 1), 256, SMEM_BYTES>>>(bh);
    }

    readout_k<<<2048, 256>>>(Wa, ba, Wo, bo);
    finalize_k<<<4, 256>>>(out);
}

// round 5
// speedup vs baseline: 2.7219x; 1.8737x over previous
#include <cuda_runtime.h>
#include <math.h>

#define Bn 4
#define Nn 4096
#define En 16384

// ---------------------------------------------------------------------------
// Static device scratch
// ---------------------------------------------------------------------------
__device__ __align__(16) float g_AG[(size_t)Bn * Nn * 512];    // [a_in | a_out]
__device__ __align__(16) float g_RZ[(size_t)Bn * Nn * 512];    // [r*h | z]
__device__ __align__(16) float g_h[(size_t)Bn * Nn * 256];     // node state (tf32-rounded)
__device__ __align__(16) float g_ann[(size_t)Bn * Nn * 64];
__device__ __align__(16) float g_Wt[16 * 256 * 256];           // rounded edge_embed
__device__ __align__(16) float g_Wrz[512 * 768];               // rounded [Wr;Wz]
__device__ __align__(16) float g_Wh[256 * 768];                // rounded Wh
__device__ __align__(16) float g_brz[512];
__device__ float g_nodeval[Bn * Nn];
// edge sort (by batch*8 + etype), done once per call
__device__ int g_cnt[32];
__device__ int g_cur[32];
__device__ int g_off[33];
__device__ int g_eidx[Bn * En];

// ---------------------------------------------------------------------------
// Helpers
// ---------------------------------------------------------------------------
__device__ __forceinline__ unsigned f2tf(float x) {
    unsigned r;
    asm("cvt.rna.tf32.f32 %0, %1;" : "=r"(r) : "f"(x));
    return r;
}
__device__ __forceinline__ float roundtf(float x) { return __uint_as_float(f2tf(x)); }

__device__ __forceinline__ void mma1688(float* c, const unsigned* a, const unsigned* b) {
    asm volatile(
        "mma.sync.aligned.m16n8k8.row.col.f32.tf32.tf32.f32 "
        "{%0,%1,%2,%3}, {%4,%5,%6,%7}, {%8,%9}, {%0,%1,%2,%3};"
        : "+f"(c[0]), "+f"(c[1]), "+f"(c[2]), "+f"(c[3])
        : "r"(a[0]), "r"(a[1]), "r"(a[2]), "r"(a[3]), "r"(b[0]), "r"(b[1]));
}

__device__ __forceinline__ void redadd2(float* p, float x, float y) {
    asm volatile("red.global.add.v2.f32 [%0], {%1,%2};"
                 :: "l"(p), "f"(x), "f"(y) : "memory");
}

#define SMS 36                      // [m][k] stride: conflict-free scalar frag LDS
#define STAGE (128 * SMS)
#define SMEM_BYTES (4 * STAGE * 4)  // 73728 B

// ---------------------------------------------------------------------------
// Sort edges by (batch, etype) -> 32 bins. Edges constant across steps.
// ---------------------------------------------------------------------------
__global__ void zero_sort_k() {
    int i = threadIdx.x;
    if (i < 32) { g_cnt[i] = 0; g_cur[i] = 0; }
}
__global__ void hist_k(const int* __restrict__ et) {
    int e = blockIdx.x * 256 + threadIdx.x;      // 65536
    atomicAdd(&g_cnt[(e >> 14) * 8 + et[e]], 1);
}
__global__ void scan_k() {
    int i = threadIdx.x;  // 32
    int s = g_cnt[i];
#pragma unroll
    for (int d = 1; d < 32; d <<= 1) {
        int u = __shfl_up_sync(0xffffffffu, s, d);
        if (i >= d) s += u;
    }
    g_off[i + 1] = s;
    if (i == 0) g_off[0] = 0;
}
__global__ void build_k(const int* __restrict__ et) {
    int e = blockIdx.x * 256 + threadIdx.x;
    int bin = (e >> 14) * 8 + et[e];
    int pos = g_off[bin] + atomicAdd(&g_cur[bin], 1);
    g_eidx[pos] = e;
}

// ---------------------------------------------------------------------------
// Gather-GEMM with fused scatter: for group (b,t) and direction dir,
//   rows = edges e of that group
//   dir 0 (out): A row = h[b, dst[e]], W_t,      += eb[t],   scatter a_out[src[e]]
//   dir 1 (in):  A row = h[b, src[e]], W_{t+8},  += eb[t+8], scatter a_in [dst[e]]
// Block 128x128x32 double-buffered (same core as the dense GEMM).
// grid (128, 2, 64); blocks with m0 >= count exit.
// ---------------------------------------------------------------------------
__global__ void __launch_bounds__(256, 2) gather_gemm_k(
    const int* __restrict__ src, const int* __restrict__ dst,
    const float* __restrict__ eb, int K)
{
    int zz = blockIdx.z;
    int grp = zz >> 1, dir = zz & 1;
    int b = grp >> 3, t = grp & 7;
    int off = g_off[grp];
    int cnt = g_off[grp + 1] - off;
    int m0 = blockIdx.x * 128;
    if (m0 >= cnt) return;

    extern __shared__ float sm[];
    float* As = sm;
    float* Bs = sm + 2 * STAGE;

    const int tid = threadIdx.x;
    const int wid = tid >> 5, lane = tid & 31;
    const int g = lane >> 2, tg = lane & 3;
    const int wm = (wid >> 2) * 64;
    const int wn = (wid & 3) * 32;
    const int n0 = blockIdx.y * 128;
    const int lr = tid >> 3;
    const int lc = (tid & 7) << 2;

    const int* gidx = dir ? src : dst;
    const int* sidx = dir ? dst : src;
    const float* W = g_Wt + (size_t)(t + dir * 8) * 65536;
    const float* bias = eb + (size_t)(t + dir * 8) * 256;
    const float* hb = g_h + (size_t)b * Nn * 256;
    float* agb = g_AG + (size_t)b * Nn * 512 + (dir ? 0 : 256);

    // gathered A row pointers (clamped; out-of-range rows masked in epilogue)
    const float* Ap[4];
#pragma unroll
    for (int r = 0; r < 4; r++) {
        int mg = m0 + lr + r * 32;
        if (mg >= cnt) mg = cnt - 1;
        int e = g_eidx[off + mg];
        Ap[r] = hb + (size_t)gidx[e] * 256 + lc;
    }
    const float* Bg = W + (size_t)(n0 + lr) * 256 + lc;

    float acc[4][4][4];
#pragma unroll
    for (int mt = 0; mt < 4; mt++)
#pragma unroll
        for (int nt = 0; nt < 4; nt++)
#pragma unroll
            for (int c = 0; c < 4; c++) acc[mt][nt][c] = 0.f;

    const int KT = K >> 5;
    float4 pa[4], pb[4];
#pragma unroll
    for (int r = 0; r < 4; r++) {
        pa[r] = *(const float4*)Ap[r];
        pb[r] = *(const float4*)(Bg + (size_t)(r * 32) * 256);
    }

    for (int kt = 0; kt < KT; kt++) {
        float* Aw = As + (kt & 1) * STAGE;
        float* Bw = Bs + (kt & 1) * STAGE;
#pragma unroll
        for (int r = 0; r < 4; r++) {
            *(float4*)(Aw + (lr + r * 32) * SMS + lc) = pa[r];
            *(float4*)(Bw + (lr + r * 32) * SMS + lc) = pb[r];
        }
        if (kt + 1 < KT) {
#pragma unroll
            for (int r = 0; r < 4; r++) {
                pa[r] = *(const float4*)(Ap[r] + (kt + 1) * 32);
                pb[r] = *(const float4*)(Bg + (kt + 1) * 32 + (size_t)(r * 32) * 256);
            }
        }
        __syncthreads();
        const float* Ac = Aw;
        const float* Bc = Bw;
#pragma unroll
        for (int ks = 0; ks < 4; ks++) {
            const int kc = ks * 8 + tg;
            unsigned bf[4][2];
#pragma unroll
            for (int nt = 0; nt < 4; nt++) {
                int col = wn + nt * 8 + g;
                bf[nt][0] = __float_as_uint(Bc[col * SMS + kc]);
                bf[nt][1] = __float_as_uint(Bc[col * SMS + kc + 4]);
            }
#pragma unroll
            for (int mt = 0; mt < 4; mt++) {
                int row = wm + mt * 16 + g;
                unsigned af[4];
                af[0] = __float_as_uint(Ac[row * SMS + kc]);
                af[1] = __float_as_uint(Ac[(row + 8) * SMS + kc]);
                af[2] = __float_as_uint(Ac[row * SMS + kc + 4]);
                af[3] = __float_as_uint(Ac[(row + 8) * SMS + kc + 4]);
#pragma unroll
                for (int nt = 0; nt < 4; nt++)
                    mma1688(acc[mt][nt], af, bf[nt]);
            }
        }
        __syncthreads();
    }

    // epilogue: add per-edge-type bias, scatter-add into AG
#pragma unroll
    for (int mt = 0; mt < 4; mt++) {
        int mrow = m0 + wm + mt * 16 + g;
#pragma unroll
        for (int nt = 0; nt < 4; nt++) {
            int colg = n0 + wn + nt * 8 + 2 * tg;
            float b0 = bias[colg], b1 = bias[colg + 1];
            if (mrow < cnt) {
                int e = g_eidx[off + mrow];
                int sn = sidx[e];
                redadd2(agb + (size_t)sn * 512 + colg,
                        acc[mt][nt][0] + b0, acc[mt][nt][1] + b1);
            }
            if (mrow + 8 < cnt) {
                int e = g_eidx[off + mrow + 8];
                int sn = sidx[e];
                redadd2(agb + (size_t)sn * 512 + colg,
                        acc[mt][nt][2] + b0, acc[mt][nt][3] + b1);
            }
        }
    }
}

// ---------------------------------------------------------------------------
// Split-A TF32 GEMM core: A logical row = [ AG row (512 cols) | A2 row (256 cols) ]
// K = 768 fixed. C[m,n] = act( sum_k A[m,k]*B[n,k] + bias[n] ).
// ACT 1 (rz):  col<256 -> RZ[row][col] = round(sigmoid(v) * h[row][col])  (A2 = h)
//              col>=256 -> RZ[row][col] = sigmoid(v)                      (z)
// ACT 2 (hh):  h[row][col] = round((1-z)h + z*tanh(v))  (A2 = RZ r*h, Zp = z)
// No kernel reads memory that it (or a sibling block) writes.
// ---------------------------------------------------------------------------
template <int ACT>
__device__ __forceinline__ void gemm_core(const float* __restrict__ A, int lda,
                                          const float* __restrict__ A2, int lda2,
                                          const float* __restrict__ B, int ldb,
                                          float* __restrict__ C, int ldc,
                                          const float* __restrict__ bias,
                                          const float* __restrict__ Zp,
                                          float* __restrict__ Hp)
{
    extern __shared__ float sm[];
    float* As = sm;
    float* Bs = sm + 2 * STAGE;

    const int tid = threadIdx.x;
    const int wid = tid >> 5, lane = tid & 31;
    const int g = lane >> 2, tg = lane & 3;
    const int wm = (wid >> 2) * 64;
    const int wn = (wid & 3) * 32;
    const int m0 = blockIdx.x * 128;
    const int n0 = blockIdx.y * 128;
    const int lr = tid >> 3;
    const int lc = (tid & 7) << 2;

    float acc[4][4][4];
#pragma unroll
    for (int mt = 0; mt < 4; mt++)
#pragma unroll
        for (int nt = 0; nt < 4; nt++)
#pragma unroll
            for (int c = 0; c < 4; c++) acc[mt][nt][c] = 0.f;

    const float* Bg = B + (size_t)(n0 + lr) * ldb + lc;
    const int KT = 6;  // K = 768

    // A source pointer for k-tile kt, row-group r (k<512 from A, else A2)
    auto arow = [&](int kt, int r) -> const float* {
        int k = kt * 32;
        int row = m0 + lr + r * 32;
        return (k < 512) ? A + (size_t)row * lda + k + lc
                         : A2 + (size_t)row * lda2 + (k - 512) + lc;
    };

    float4 pa[4], pb[4];
#pragma unroll
    for (int r = 0; r < 4; r++) {
        pa[r] = *(const float4*)arow(0, r);
        pb[r] = *(const float4*)(Bg + (size_t)(r * 32) * ldb);
    }

    for (int kt = 0; kt < KT; kt++) {
        float* Aw = As + (kt & 1) * STAGE;
        float* Bw = Bs + (kt & 1) * STAGE;
#pragma unroll
        for (int r = 0; r < 4; r++) {
            *(float4*)(Aw + (lr + r * 32) * SMS + lc) = pa[r];
            *(float4*)(Bw + (lr + r * 32) * SMS + lc) = pb[r];
        }
        if (kt + 1 < KT) {
#pragma unroll
            for (int r = 0; r < 4; r++) {
                pa[r] = *(const float4*)arow(kt + 1, r);
                pb[r] = *(const float4*)(Bg + (kt + 1) * 32 + (size_t)(r * 32) * ldb);
            }
        }
        __syncthreads();
        const float* Ac = Aw;
        const float* Bc = Bw;
#pragma unroll
        for (int ks = 0; ks < 4; ks++) {
            const int kc = ks * 8 + tg;
            unsigned bf[4][2];
#pragma unroll
            for (int nt = 0; nt < 4; nt++) {
                int col = wn + nt * 8 + g;
                bf[nt][0] = __float_as_uint(Bc[col * SMS + kc]);
                bf[nt][1] = __float_as_uint(Bc[col * SMS + kc + 4]);
            }
#pragma unroll
            for (int mt = 0; mt < 4; mt++) {
                int row = wm + mt * 16 + g;
                unsigned af[4];
                af[0] = __float_as_uint(Ac[row * SMS + kc]);
                af[1] = __float_as_uint(Ac[(row + 8) * SMS + kc]);
                af[2] = __float_as_uint(Ac[row * SMS + kc + 4]);
                af[3] = __float_as_uint(Ac[(row + 8) * SMS + kc + 4]);
#pragma unroll
                for (int nt = 0; nt < 4; nt++)
                    mma1688(acc[mt][nt], af, bf[nt]);
            }
        }
        __syncthreads();
    }

#pragma unroll
    for (int mt = 0; mt < 4; mt++) {
#pragma unroll
        for (int nt = 0; nt < 4; nt++) {
            int row = m0 + wm + mt * 16 + g;
            int col = n0 + wn + nt * 8 + 2 * tg;
            float b0 = bias[col], b1 = bias[col + 1];
            float v0 = acc[mt][nt][0] + b0, v1 = acc[mt][nt][1] + b1;
            float v2 = acc[mt][nt][2] + b0, v3 = acc[mt][nt][3] + b1;
            if (ACT == 1) {
                float s0 = 1.f / (1.f + expf(-v0)), s1 = 1.f / (1.f + expf(-v1));
                float s2 = 1.f / (1.f + expf(-v2)), s3 = 1.f / (1.f + expf(-v3));
                float* p0 = C + (size_t)row * ldc + col;
                float* p1 = C + (size_t)(row + 8) * ldc + col;
                if (col < 256) {
                    // r * h (tf32-rounded), h from Zp (= g_h)
                    const float* h0 = Zp + (size_t)row * 256 + col;
                    const float* h1 = Zp + (size_t)(row + 8) * 256 + col;
                    *(float2*)p0 = make_float2(roundtf(s0 * h0[0]), roundtf(s1 * h0[1]));
                    *(float2*)p1 = make_float2(roundtf(s2 * h1[0]), roundtf(s3 * h1[1]));
                } else {
                    *(float2*)p0 = make_float2(s0, s1);
                    *(float2*)p1 = make_float2(s2, s3);
                }
            } else {
                // fused GRU update
                float z0 = Zp[(size_t)row * 512 + col], z1 = Zp[(size_t)row * 512 + col + 1];
                float z2 = Zp[(size_t)(row + 8) * 512 + col], z3 = Zp[(size_t)(row + 8) * 512 + col + 1];
                float* hp0 = Hp + (size_t)row * 256 + col;
                float* hp1 = Hp + (size_t)(row + 8) * 256 + col;
                float h0 = hp0[0], h1 = hp0[1], h2 = hp1[0], h3 = hp1[1];
                *(float2*)hp0 = make_float2(roundtf((1.f - z0) * h0 + z0 * tanhf(v0)),
                                            roundtf((1.f - z1) * h1 + z1 * tanhf(v1)));
                *(float2*)hp1 = make_float2(roundtf((1.f - z2) * h2 + z2 * tanhf(v2)),
                                            roundtf((1.f - z3) * h3 + z3 * tanhf(v3)));
            }
        }
    }
}

__global__ void __launch_bounds__(256, 2) gemm_rz_k() {
    // A = [AG | h], B = Wrz; r*h -> RZ[:, :256], z -> RZ[:, 256:]
    gemm_core<1>(g_AG, 512, g_h, 256, g_Wrz, 768, g_RZ, 512, g_brz, g_h, nullptr);
}

__global__ void __launch_bounds__(256, 2) gemm_hh_k(const float* __restrict__ bh) {
    // A = [AG | r*h], B = Wh; fused update writes g_h
    gemm_core<2>(g_AG, 512, g_RZ, 512, g_Wh, 768, nullptr, 0, bh, g_RZ + 256, g_h);
}

// ---------------------------------------------------------------------------
// Setup kernels
// ---------------------------------------------------------------------------
__global__ void prep_Wt(const float* __restrict__ ee) {
    size_t i = (size_t)blockIdx.x * 256 + threadIdx.x;
    g_Wt[i] = roundtf(ee[i]);
}
__global__ void prep_Wrz(const float* __restrict__ Wr, const float* __restrict__ Wz,
                         const float* __restrict__ br, const float* __restrict__ bz) {
    int r = blockIdx.x;  // 512
    const float* s = (r < 256) ? (Wr + (size_t)r * 768) : (Wz + (size_t)(r - 256) * 768);
    for (int c = threadIdx.x; c < 768; c += blockDim.x)
        g_Wrz[(size_t)r * 768 + c] = roundtf(s[c]);
    if (threadIdx.x == 0) g_brz[r] = (r < 256) ? br[r] : bz[r - 256];
}
__global__ void prep_Wh(const float* __restrict__ Wh) {
    size_t i = (size_t)blockIdx.x * 256 + threadIdx.x;
    g_Wh[i] = roundtf(Wh[i]);
}
__global__ void init_h(const int* __restrict__ ann_id, const float* __restrict__ te) {
    int n = blockIdx.x;
    int i = threadIdx.x;
    int id = ann_id[n];
    float a = 0.f;
    if (i < 64 && id > 0) a = te[(size_t)(id - 1) * 64 + i];
    if (i < 64) g_ann[(size_t)n * 64 + i] = a;
    g_h[(size_t)n * 256 + i] = (i < 64) ? roundtf(a) : 0.f;
}

// zero AG (a_in | a_out): 4*4096*512 floats = 2097152 float4 -> grid 8192
__global__ void prep_AG() {
    size_t i = (size_t)blockIdx.x * 256 + threadIdx.x;
    ((float4*)g_AG)[i] = make_float4(0.f, 0.f, 0.f, 0.f);
}

// ---------------------------------------------------------------------------
// Readout
// ---------------------------------------------------------------------------
__global__ void readout_k(const float* __restrict__ Wa, const float* __restrict__ ba,
                          const float* __restrict__ Wo, const float* __restrict__ bo) {
    int warp = (blockIdx.x * blockDim.x + threadIdx.x) >> 5;
    int lane = threadIdx.x & 31;
    const float* hrow = g_h + (size_t)warp * 256;
    const float* arow = g_ann + (size_t)warp * 64;
    float sa = 0.f, so = 0.f;
#pragma unroll
    for (int k = lane; k < 320; k += 32) {
        float v = (k < 256) ? hrow[k] : arow[k - 256];
        sa += v * Wa[k];
        so += v * Wo[k];
    }
#pragma unroll
    for (int off = 16; off; off >>= 1) {
        sa += __shfl_xor_sync(0xffffffffu, sa, off);
        so += __shfl_xor_sync(0xffffffffu, so, off);
    }
    if (lane == 0) {
        float atten = 1.f / (1.f + expf(-(sa + ba[0])));
        float ou = tanhf(so + bo[0]);
        g_nodeval[warp] = atten * ou;
    }
}

__global__ void finalize_k(float* __restrict__ out) {
    __shared__ float sh[256];
    int b = blockIdx.x;
    float s = 0.f;
    for (int i = threadIdx.x; i < Nn; i += 256) s += g_nodeval[(size_t)b * Nn + i];
    sh[threadIdx.x] = s;
    __syncthreads();
    for (int k = 128; k; k >>= 1) {
        if (threadIdx.x < k) sh[threadIdx.x] += sh[threadIdx.x + k];
        __syncthreads();
    }
    if (threadIdx.x == 0) out[b] = 1.f / (1.f + expf(-sh[0]));
}

// ---------------------------------------------------------------------------
// Launch
// ---------------------------------------------------------------------------
extern "C" void kernel_launch(void* const* d_in, const int* in_sizes, int n_in,
                              void* d_out, int out_size) {
    (void)in_sizes; (void)n_in; (void)out_size;
    const int* ann_id = (const int*)d_in[0];
    const int* src    = (const int*)d_in[1];
    const int* dst    = (const int*)d_in[2];
    const int* et     = (const int*)d_in[3];
    const float* ee   = (const float*)d_in[4];
    const float* eb   = (const float*)d_in[5];
    const float* te   = (const float*)d_in[6];
    const float* Wr   = (const float*)d_in[7];
    const float* br   = (const float*)d_in[8];
    const float* Wz   = (const float*)d_in[9];
    const float* bz   = (const float*)d_in[10];
    const float* Wh   = (const float*)d_in[11];
    const float* bh   = (const float*)d_in[12];
    const float* Wa   = (const float*)d_in[13];
    const float* ba   = (const float*)d_in[14];
    const float* Wo   = (const float*)d_in[15];
    const float* bo   = (const float*)d_in[16];
    float* out = (float*)d_out;

    cudaFuncSetAttribute(gather_gemm_k, cudaFuncAttributeMaxDynamicSharedMemorySize, SMEM_BYTES);
    cudaFuncSetAttribute(gemm_rz_k, cudaFuncAttributeMaxDynamicSharedMemorySize, SMEM_BYTES);
    cudaFuncSetAttribute(gemm_hh_k, cudaFuncAttributeMaxDynamicSharedMemorySize, SMEM_BYTES);

    prep_Wt<<<4096, 256>>>(ee);
    prep_Wrz<<<512, 256>>>(Wr, Wz, br, bz);
    prep_Wh<<<768, 256>>>(Wh);
    init_h<<<Bn * Nn, 256>>>(ann_id, te);

    // edge sort (once; edges constant across steps)
    zero_sort_k<<<1, 32>>>();
    hist_k<<<256, 256>>>(et);
    scan_k<<<1, 32>>>();
    build_k<<<256, 256>>>(et);

    for (int step = 0; step < 3; step++) {
        prep_AG<<<8192, 256>>>();
        // step 0: h has only 64 nonzero columns -> K=64 exact
        gather_gemm_k<<<dim3(128, 2, 64), 256, SMEM_BYTES>>>(src, dst, eb,
                                                             step == 0 ? 64 : 256);
        gemm_rz_k<<<dim3(128, 4, 1), 256, SMEM_BYTES>>>();
        gemm_hh_k<<<dim3(128, 2, 1), 256, SMEM_BYTES>>>(bh);
    }

    readout_k<<<2048, 256>>>(Wa, ba, Wo, bo);
    finalize_k<<<4, 256>>>(out);
}